// round 1
// baseline (speedup 1.0000x reference)
#include <cuda_runtime.h>
#include <math.h>

#define Bv 2
#define Sv 2048
#define Dv 1024
#define Hv 16
#define HDv 64
#define HIDv 256
#define DYNv 64
#define RKv 8
#define Mv (Bv*Sv)

// ---------------- scratch (device globals; no allocation allowed) ----------------
__device__ float g_zpart[Bv*8*Dv];
__device__ float g_z[Bv*Dv];
__device__ float g_h[2*Bv*HIDv];
__device__ float g_c[2*Bv*DYNv];
__device__ float g_A[2*Bv*RKv*Dv];
__device__ float g_Bm[2*Bv*Dv*RKv];
__device__ float g_Weff[2*Bv*Dv*Dv];   // 16 MB: [kv][b][D][D]
__device__ float g_q[Mv*Dv];
__device__ float g_k[Mv*Dv];
__device__ float g_v[Mv*Dv];
__device__ float g_qh[Mv*Dv];          // (B,H,S,hd) rope'd
__device__ float g_kh[Mv*Dv];
__device__ float g_vh[Mv*Dv];
__device__ float g_attn[Mv*Dv];        // (B,S,D)

// ---------------- 1) pooled context z = mean_s x ----------------
__global__ void pool_partial(const float* __restrict__ x) {
    int d = blockIdx.x*256 + threadIdx.x;   // 0..1023 (grid.x=4)
    int split = blockIdx.y;                 // 0..7
    int b = blockIdx.z;
    const float* xp = x + ((long)b*Sv + split*256)*Dv + d;
    float acc = 0.f;
    #pragma unroll 8
    for (int s = 0; s < 256; s++) acc += xp[(long)s*Dv];
    g_zpart[(b*8 + split)*Dv + d] = acc;
}

__global__ void pool_combine() {
    int idx = blockIdx.x*256 + threadIdx.x; // 0..2047
    int b = idx >> 10, d = idx & 1023;
    float acc = 0.f;
    #pragma unroll
    for (int p = 0; p < 8; p++) acc += g_zpart[(b*8 + p)*Dv + d];
    g_z[idx] = acc * (1.f / (float)Sv);
}

// ---------------- 2) hyper-network small MLP ----------------
__global__ void hyp_h(const float* __restrict__ k_w1, const float* __restrict__ k_b1,
                      const float* __restrict__ v_w1, const float* __restrict__ v_b1) {
    int kv = blockIdx.x, b = blockIdx.y, j = threadIdx.x;
    const float* w1 = kv ? v_w1 : k_w1;
    const float* b1 = kv ? v_b1 : k_b1;
    const float* zb = g_z + b*Dv;
    float acc = b1[j];
    #pragma unroll 4
    for (int d = 0; d < Dv; d++) acc += zb[d] * w1[d*HIDv + j];
    float sg = 1.f / (1.f + __expf(-acc));
    g_h[(kv*Bv + b)*HIDv + j] = acc * sg;   // silu
}

__global__ void hyp_c(const float* __restrict__ k_w2, const float* __restrict__ k_b2,
                      const float* __restrict__ v_w2, const float* __restrict__ v_b2) {
    int kv = blockIdx.x, b = blockIdx.y, j = threadIdx.x;
    const float* w2 = kv ? v_w2 : k_w2;
    const float* b2 = kv ? v_b2 : k_b2;
    const float* hb = g_h + (kv*Bv + b)*HIDv;
    float acc = b2[j];
    #pragma unroll 4
    for (int i = 0; i < HIDv; i++) acc += hb[i] * w2[i*DYNv + j];
    g_c[(kv*Bv + b)*DYNv + j] = acc;
}

__global__ void hyp_AB(const float* __restrict__ kAw, const float* __restrict__ kAb,
                       const float* __restrict__ kBw, const float* __restrict__ kBb,
                       const float* __restrict__ vAw, const float* __restrict__ vAb,
                       const float* __restrict__ vBw, const float* __restrict__ vBb) {
    int kv = blockIdx.x, b = blockIdx.y, chunk = blockIdx.z;  // z: 0..63
    const float* cc = g_c + (kv*Bv + b)*DYNv;
    bool isA = chunk < 32;
    int j = (isA ? chunk : chunk - 32)*256 + threadIdx.x;     // 0..8191
    const float* w  = isA ? (kv ? vAw : kAw) : (kv ? vBw : kBw);
    const float* bb = isA ? (kv ? vAb : kAb) : (kv ? vBb : kBb);
    float acc = bb[j];
    #pragma unroll 8
    for (int t = 0; t < DYNv; t++) acc += cc[t] * w[t*(RKv*Dv) + j];
    float* dst = isA ? g_A : g_Bm;
    dst[(kv*Bv + b)*(RKv*Dv) + j] = acc;
}

// ---------------- 3) fold low-rank into effective weight ----------------
// Weff[d][o] = W[d][o] + (1/RANK) * sum_r A[r][d] * Bm[o][r]
__global__ void weff_kernel(const float* __restrict__ Wk, const float* __restrict__ Wv) {
    int kv = blockIdx.z, b = blockIdx.y;
    int idx = blockIdx.x*256 + threadIdx.x;     // 0..(1M-1)
    int d = idx >> 10, o = idx & 1023;
    const float* W  = kv ? Wv : Wk;
    const float* Ap = g_A  + (kv*Bv + b)*(RKv*Dv);
    const float* Bp = g_Bm + (kv*Bv + b)*(Dv*RKv);
    float acc = 0.f;
    #pragma unroll
    for (int r = 0; r < RKv; r++) acc += Ap[r*Dv + d] * Bp[o*RKv + r];
    g_Weff[((long)(kv*Bv + b))*(Dv*Dv) + idx] = W[idx] + 0.125f * acc;
}

// ---------------- 4) SGEMM: C = A(MxK) @ W(KxN) + bias ----------------
__global__ void __launch_bounds__(256, 2) sgemm_bias(
    const float* __restrict__ A, const float* __restrict__ W,
    const float* __restrict__ bias, float* __restrict__ C,
    int M, int N, int K, long sA, long sW, long sC)
{
    A += (long)blockIdx.z * sA;
    W += (long)blockIdx.z * sW;
    C += (long)blockIdx.z * sC;
    __shared__ float As[8][128];   // transposed: As[k][m]
    __shared__ float Ws[8][128];
    const int tid  = threadIdx.x;
    const int brow = blockIdx.y * 128;
    const int bcol = blockIdx.x * 128;
    const int arow = tid >> 1;
    const int acol = (tid & 1) * 4;
    const int wrow = tid >> 5;
    const int wcol = (tid & 31) * 4;
    const int ty = tid >> 4, tx = tid & 15;

    float acc[8][8];
    #pragma unroll
    for (int i = 0; i < 8; i++)
        #pragma unroll
        for (int j = 0; j < 8; j++) acc[i][j] = 0.f;

    const float* Ag = A + (long)(brow + arow)*K + acol;
    const float* Wg = W + (long)wrow*N + bcol + wcol;

    for (int k0 = 0; k0 < K; k0 += 8) {
        float4 a4 = *(const float4*)(Ag + k0);
        float4 w4 = *(const float4*)(Wg + (long)k0*N);
        As[acol+0][arow] = a4.x; As[acol+1][arow] = a4.y;
        As[acol+2][arow] = a4.z; As[acol+3][arow] = a4.w;
        *(float4*)&Ws[wrow][wcol] = w4;
        __syncthreads();
        #pragma unroll
        for (int kk = 0; kk < 8; kk++) {
            float4 a0 = *(const float4*)&As[kk][ty*4];
            float4 a1 = *(const float4*)&As[kk][64 + ty*4];
            float4 b0 = *(const float4*)&Ws[kk][tx*4];
            float4 b1 = *(const float4*)&Ws[kk][64 + tx*4];
            float av[8] = {a0.x,a0.y,a0.z,a0.w,a1.x,a1.y,a1.z,a1.w};
            float bv[8] = {b0.x,b0.y,b0.z,b0.w,b1.x,b1.y,b1.z,b1.w};
            #pragma unroll
            for (int i = 0; i < 8; i++)
                #pragma unroll
                for (int j = 0; j < 8; j++)
                    acc[i][j] += av[i] * bv[j];
        }
        __syncthreads();
    }
    #pragma unroll
    for (int i = 0; i < 8; i++) {
        int r = brow + ((i < 4) ? ty*4 + i : 64 + ty*4 + (i - 4));
        #pragma unroll
        for (int j = 0; j < 8; j++) {
            int cc = bcol + ((j < 4) ? tx*4 + j : 64 + tx*4 + (j - 4));
            C[(long)r*N + cc] = acc[i][j] + bias[cc];
        }
    }
}

// ---------------- 5) rope + head-split transpose ----------------
__global__ void rope_kernel() {
    int idx = blockIdx.x*256 + threadIdx.x;   // < B*H*S*32 = 2M
    int d2 = idx & 31;
    int s  = (idx >> 5) & 2047;
    int h  = (idx >> 16) & 15;
    int b  = idx >> 20;
    long src = ((long)(b*Sv + s))*Dv + h*HDv;
    long dst = ((long)((b*Hv + h)*Sv + s))*HDv;
    float inv = expf(-((float)d2 * (1.f/32.f)) * 9.210340371976184f);  // 10000^(-d2/32)
    float ang = (float)s * inv;
    float sn, cs;
    sincosf(ang, &sn, &cs);
    float q0 = g_q[src + d2], q1 = g_q[src + d2 + 32];
    g_qh[dst + d2]      = q0*cs - q1*sn;
    g_qh[dst + d2 + 32] = q1*cs + q0*sn;
    float k0 = g_k[src + d2], k1 = g_k[src + d2 + 32];
    g_kh[dst + d2]      = k0*cs - k1*sn;
    g_kh[dst + d2 + 32] = k1*cs + k0*sn;
    g_vh[dst + d2]      = g_v[src + d2];
    g_vh[dst + d2 + 32] = g_v[src + d2 + 32];
}

// ---------------- 6) causal flash attention (fp32, 64x64 tiles) ----------------
#define FLASH_SMEM_FLOATS (64*65*3 + 64*64 + 3*64)
__global__ void __launch_bounds__(256) flash_kernel(
    const float* __restrict__ Q, const float* __restrict__ K,
    const float* __restrict__ V, float* __restrict__ Out)
{
    extern __shared__ float sm[];
    float* Qt   = sm;               // [64][65] transposed Qt[d*65+r]
    float* Kt   = Qt + 64*65;       // [64][65] transposed
    float* Vs   = Kt + 64*65;       // [64][64] row-major
    float* Ss   = Vs + 64*64;       // [64][65]
    float* mrow = Ss + 64*65;
    float* lrow = mrow + 64;
    float* arow = lrow + 64;

    const int qt = blockIdx.x;
    const int bh = blockIdx.y;
    const int tid = threadIdx.x;
    const int ty = tid >> 4, tx = tid & 15;

    const float* Qb = Q + ((long)bh*Sv + qt*64)*HDv;
    const float* Kb = K + (long)bh*Sv*HDv;
    const float* Vb = V + (long)bh*Sv*HDv;

    #pragma unroll
    for (int it = 0; it < 4; it++) {
        int i = tid + it*256;
        int r = i >> 4, d4 = (i & 15)*4;
        float4 qv = *(const float4*)(Qb + r*HDv + d4);
        Qt[(d4+0)*65 + r] = qv.x; Qt[(d4+1)*65 + r] = qv.y;
        Qt[(d4+2)*65 + r] = qv.z; Qt[(d4+3)*65 + r] = qv.w;
    }
    if (tid < 64) { mrow[tid] = -1e30f; lrow[tid] = 0.f; }

    float oacc[4][4];
    #pragma unroll
    for (int i = 0; i < 4; i++)
        #pragma unroll
        for (int j = 0; j < 4; j++) oacc[i][j] = 0.f;

    for (int jt = 0; jt <= qt; jt++) {
        #pragma unroll
        for (int it = 0; it < 4; it++) {
            int i = tid + it*256;
            int r = i >> 4, d4 = (i & 15)*4;
            float4 k4 = *(const float4*)(Kb + ((long)(jt*64 + r))*HDv + d4);
            Kt[(d4+0)*65 + r] = k4.x; Kt[(d4+1)*65 + r] = k4.y;
            Kt[(d4+2)*65 + r] = k4.z; Kt[(d4+3)*65 + r] = k4.w;
            float4 v4 = *(const float4*)(Vb + ((long)(jt*64 + r))*HDv + d4);
            *(float4*)(Vs + r*64 + d4) = v4;
        }
        __syncthreads();

        // phase A: S = Q @ K^T
        float sacc[4][4];
        #pragma unroll
        for (int i = 0; i < 4; i++)
            #pragma unroll
            for (int j = 0; j < 4; j++) sacc[i][j] = 0.f;
        #pragma unroll 8
        for (int d = 0; d < 64; d++) {
            const float* qr = Qt + d*65 + ty*4;
            const float* kr = Kt + d*65 + tx*4;
            float a0 = qr[0], a1 = qr[1], a2 = qr[2], a3 = qr[3];
            float b0 = kr[0], b1 = kr[1], b2 = kr[2], b3 = kr[3];
            sacc[0][0] += a0*b0; sacc[0][1] += a0*b1; sacc[0][2] += a0*b2; sacc[0][3] += a0*b3;
            sacc[1][0] += a1*b0; sacc[1][1] += a1*b1; sacc[1][2] += a1*b2; sacc[1][3] += a1*b3;
            sacc[2][0] += a2*b0; sacc[2][1] += a2*b1; sacc[2][2] += a2*b2; sacc[2][3] += a2*b3;
            sacc[3][0] += a3*b0; sacc[3][1] += a3*b1; sacc[3][2] += a3*b2; sacc[3][3] += a3*b3;
        }
        #pragma unroll
        for (int i = 0; i < 4; i++) {
            int r = ty*4 + i;
            #pragma unroll
            for (int j = 0; j < 4; j++) {
                int c = tx*4 + j;
                float s = sacc[i][j] * 0.125f;
                if (jt == qt && c > r) s = -1e30f;
                Ss[r*65 + c] = s;
            }
        }
        __syncthreads();

        // phase B: online softmax (4 threads per row)
        {
            int r = tid >> 2, q4 = tid & 3;
            float* row = Ss + r*65 + q4*16;
            float vb[16];
            float mx = -1e30f;
            #pragma unroll
            for (int t = 0; t < 16; t++) { vb[t] = row[t]; mx = fmaxf(mx, vb[t]); }
            mx = fmaxf(mx, __shfl_xor_sync(0xffffffffu, mx, 1));
            mx = fmaxf(mx, __shfl_xor_sync(0xffffffffu, mx, 2));
            float mold = mrow[r];
            float mnew = fmaxf(mold, mx);
            float ls = 0.f;
            #pragma unroll
            for (int t = 0; t < 16; t++) {
                float p = __expf(vb[t] - mnew);
                row[t] = p; ls += p;
            }
            ls += __shfl_xor_sync(0xffffffffu, ls, 1);
            ls += __shfl_xor_sync(0xffffffffu, ls, 2);
            if (q4 == 0) {
                float al = __expf(mold - mnew);
                arow[r] = al;
                mrow[r] = mnew;
                lrow[r] = lrow[r]*al + ls;
            }
        }
        __syncthreads();

        // phase C: O = O*alpha + P @ V
        #pragma unroll
        for (int i = 0; i < 4; i++) {
            float al = arow[ty*4 + i];
            #pragma unroll
            for (int j = 0; j < 4; j++) oacc[i][j] *= al;
        }
        #pragma unroll 8
        for (int kk = 0; kk < 64; kk++) {
            float p0 = Ss[(ty*4+0)*65 + kk];
            float p1 = Ss[(ty*4+1)*65 + kk];
            float p2 = Ss[(ty*4+2)*65 + kk];
            float p3 = Ss[(ty*4+3)*65 + kk];
            float4 vv = *(const float4*)(Vs + kk*64 + tx*4);
            oacc[0][0] += p0*vv.x; oacc[0][1] += p0*vv.y; oacc[0][2] += p0*vv.z; oacc[0][3] += p0*vv.w;
            oacc[1][0] += p1*vv.x; oacc[1][1] += p1*vv.y; oacc[1][2] += p1*vv.z; oacc[1][3] += p1*vv.w;
            oacc[2][0] += p2*vv.x; oacc[2][1] += p2*vv.y; oacc[2][2] += p2*vv.z; oacc[2][3] += p2*vv.w;
            oacc[3][0] += p3*vv.x; oacc[3][1] += p3*vv.y; oacc[3][2] += p3*vv.z; oacc[3][3] += p3*vv.w;
        }
        __syncthreads();
    }

    const int b = bh >> 4, h = bh & 15;
    #pragma unroll
    for (int i = 0; i < 4; i++) {
        int srow = qt*64 + ty*4 + i;
        float inv_l = 1.f / lrow[ty*4 + i];
        #pragma unroll
        for (int j = 0; j < 4; j++)
            Out[((long)(b*Sv + srow))*Dv + h*HDv + tx*4 + j] = oacc[i][j] * inv_l;
    }
}

// ---------------- launch ----------------
extern "C" void kernel_launch(void* const* d_in, const int* in_sizes, int n_in,
                              void* d_out, int out_size) {
    const float* x      = (const float*)d_in[0];
    const float* Wq     = (const float*)d_in[1];
    const float* bq     = (const float*)d_in[2];
    const float* Wo     = (const float*)d_in[3];
    const float* bo     = (const float*)d_in[4];
    const float* Wk     = (const float*)d_in[5];
    const float* bk     = (const float*)d_in[6];
    const float* k_w1   = (const float*)d_in[7];
    const float* k_b1   = (const float*)d_in[8];
    const float* k_w2   = (const float*)d_in[9];
    const float* k_b2   = (const float*)d_in[10];
    const float* k_gA_w = (const float*)d_in[11];
    const float* k_gA_b = (const float*)d_in[12];
    const float* k_gB_w = (const float*)d_in[13];
    const float* k_gB_b = (const float*)d_in[14];
    const float* Wv     = (const float*)d_in[15];
    const float* bv     = (const float*)d_in[16];
    const float* v_w1   = (const float*)d_in[17];
    const float* v_b1   = (const float*)d_in[18];
    const float* v_w2   = (const float*)d_in[19];
    const float* v_b2   = (const float*)d_in[20];
    const float* v_gA_w = (const float*)d_in[21];
    const float* v_gA_b = (const float*)d_in[22];
    const float* v_gB_w = (const float*)d_in[23];
    const float* v_gB_b = (const float*)d_in[24];
    float* out = (float*)d_out;

    float *p_weff, *p_q, *p_k, *p_v, *p_qh, *p_kh, *p_vh, *p_attn;
    cudaGetSymbolAddress((void**)&p_weff, g_Weff);
    cudaGetSymbolAddress((void**)&p_q,    g_q);
    cudaGetSymbolAddress((void**)&p_k,    g_k);
    cudaGetSymbolAddress((void**)&p_v,    g_v);
    cudaGetSymbolAddress((void**)&p_qh,   g_qh);
    cudaGetSymbolAddress((void**)&p_kh,   g_kh);
    cudaGetSymbolAddress((void**)&p_vh,   g_vh);
    cudaGetSymbolAddress((void**)&p_attn, g_attn);

    const int flash_smem = FLASH_SMEM_FLOATS * 4;
    cudaFuncSetAttribute(flash_kernel, cudaFuncAttributeMaxDynamicSharedMemorySize, flash_smem);

    pool_partial<<<dim3(4, 8, Bv), 256>>>(x);
    pool_combine<<<8, 256>>>();
    hyp_h<<<dim3(2, Bv), HIDv>>>(k_w1, k_b1, v_w1, v_b1);
    hyp_c<<<dim3(2, Bv), DYNv>>>(k_w2, k_b2, v_w2, v_b2);
    hyp_AB<<<dim3(2, Bv, 64), 256>>>(k_gA_w, k_gA_b, k_gB_w, k_gB_b,
                                     v_gA_w, v_gA_b, v_gB_w, v_gB_b);
    weff_kernel<<<dim3(4096, Bv, 2), 256>>>(Wk, Wv);

    // q = x @ Wq + bq   (M=4096)
    sgemm_bias<<<dim3(8, 32, 1), 256>>>(x, Wq, bq, p_q, Mv, Dv, Dv, 0, 0, 0);
    // k = x @ Weff_k[b] + bk  (per batch)
    sgemm_bias<<<dim3(8, 16, Bv), 256>>>(x, p_weff, bk, p_k, Sv, Dv, Dv,
                                         (long)Sv*Dv, (long)Dv*Dv, (long)Sv*Dv);
    // v = x @ Weff_v[b] + bv
    sgemm_bias<<<dim3(8, 16, Bv), 256>>>(x, p_weff + (long)Bv*Dv*Dv, bv, p_v, Sv, Dv, Dv,
                                         (long)Sv*Dv, (long)Dv*Dv, (long)Sv*Dv);

    rope_kernel<<<8192, 256>>>();

    flash_kernel<<<dim3(32, 32), 256, flash_smem>>>(p_qh, p_kh, p_vh, p_attn);

    // out = attn @ Wo + bo
    sgemm_bias<<<dim3(8, 32, 1), 256>>>(p_attn, Wo, bo, out, Mv, Dv, Dv, 0, 0, 0);
}

// round 3
// speedup vs baseline: 1.4497x; 1.4497x over previous
#include <cuda_runtime.h>
#include <math.h>
#include <stdint.h>

#define Bv 2
#define Sv 2048
#define Dv 1024
#define Hv 16
#define HDv 64
#define HIDv 256
#define DYNv 64
#define RKv 8
#define Mv (Bv*Sv)

__device__ __forceinline__ float to_tf32(float x) {
    float r; asm("cvt.rna.tf32.f32 %0, %1;" : "=f"(r) : "f"(x)); return r;
}

#define MMA_TF32(d, a, b0, b1) \
  asm volatile("mma.sync.aligned.m16n8k8.row.col.f32.tf32.tf32.f32 " \
    "{%0,%1,%2,%3}, {%4,%5,%6,%7}, {%8,%9}, {%0,%1,%2,%3};" \
    : "+f"((d)[0]), "+f"((d)[1]), "+f"((d)[2]), "+f"((d)[3]) \
    : "r"((a)[0]), "r"((a)[1]), "r"((a)[2]), "r"((a)[3]), "r"(b0), "r"(b1))

// ---------------- scratch ----------------
__device__ float g_zpart[Bv*8*Dv];
__device__ float g_z[Bv*Dv];
__device__ float g_h[2*Bv*HIDv];
__device__ float g_c[2*Bv*DYNv];
__device__ float g_A[2*Bv*RKv*Dv];
__device__ float g_Bm[2*Bv*Dv*RKv];
__device__ float g_Weff[2*Bv*Dv*Dv];
__device__ float g_q[Mv*Dv];
__device__ float g_k[Mv*Dv];
__device__ float g_v[Mv*Dv];
__device__ float g_qh[Mv*Dv];
__device__ float g_kh[Mv*Dv];
__device__ float g_vh[Mv*Dv];
__device__ float g_attn[Mv*Dv];

// ---------------- 1) pooled context ----------------
__global__ void pool_partial(const float* __restrict__ x) {
    int d = blockIdx.x*256 + threadIdx.x;
    int split = blockIdx.y;
    int b = blockIdx.z;
    const float* xp = x + ((long)b*Sv + split*256)*Dv + d;
    float acc = 0.f;
    #pragma unroll 8
    for (int s = 0; s < 256; s++) acc += xp[(long)s*Dv];
    g_zpart[(b*8 + split)*Dv + d] = acc;
}
__global__ void pool_combine() {
    int idx = blockIdx.x*256 + threadIdx.x;
    int b = idx >> 10, d = idx & 1023;
    float acc = 0.f;
    #pragma unroll
    for (int p = 0; p < 8; p++) acc += g_zpart[(b*8 + p)*Dv + d];
    g_z[idx] = acc * (1.f / (float)Sv);
}

// ---------------- 2) hyper-network MLP ----------------
__global__ void hyp_h(const float* __restrict__ k_w1, const float* __restrict__ k_b1,
                      const float* __restrict__ v_w1, const float* __restrict__ v_b1) {
    int kv = blockIdx.x, b = blockIdx.y, j = threadIdx.x;
    const float* w1 = kv ? v_w1 : k_w1;
    const float* b1 = kv ? v_b1 : k_b1;
    const float* zb = g_z + b*Dv;
    float acc = b1[j];
    #pragma unroll 4
    for (int d = 0; d < Dv; d++) acc += zb[d] * w1[d*HIDv + j];
    float sg = 1.f / (1.f + __expf(-acc));
    g_h[(kv*Bv + b)*HIDv + j] = acc * sg;
}
__global__ void hyp_c(const float* __restrict__ k_w2, const float* __restrict__ k_b2,
                      const float* __restrict__ v_w2, const float* __restrict__ v_b2) {
    int kv = blockIdx.x, b = blockIdx.y, j = threadIdx.x;
    const float* w2 = kv ? v_w2 : k_w2;
    const float* b2 = kv ? v_b2 : k_b2;
    const float* hb = g_h + (kv*Bv + b)*HIDv;
    float acc = b2[j];
    #pragma unroll 4
    for (int i = 0; i < HIDv; i++) acc += hb[i] * w2[i*DYNv + j];
    g_c[(kv*Bv + b)*DYNv + j] = acc;
}
__global__ void hyp_AB(const float* __restrict__ kAw, const float* __restrict__ kAb,
                       const float* __restrict__ kBw, const float* __restrict__ kBb,
                       const float* __restrict__ vAw, const float* __restrict__ vAb,
                       const float* __restrict__ vBw, const float* __restrict__ vBb) {
    int kv = blockIdx.x, b = blockIdx.y, chunk = blockIdx.z;
    const float* cc = g_c + (kv*Bv + b)*DYNv;
    bool isA = chunk < 32;
    int j = (isA ? chunk : chunk - 32)*256 + threadIdx.x;
    const float* w  = isA ? (kv ? vAw : kAw) : (kv ? vBw : kBw);
    const float* bb = isA ? (kv ? vAb : kAb) : (kv ? vBb : kBb);
    float acc = bb[j];
    #pragma unroll 8
    for (int t = 0; t < DYNv; t++) acc += cc[t] * w[t*(RKv*Dv) + j];
    float* dst = isA ? g_A : g_Bm;
    dst[(kv*Bv + b)*(RKv*Dv) + j] = acc;
}

// ---------------- 3) fold low-rank into effective weight ----------------
__global__ void weff_kernel(const float* __restrict__ Wk, const float* __restrict__ Wv) {
    int kv = blockIdx.z, b = blockIdx.y;
    int idx = blockIdx.x*256 + threadIdx.x;
    int d = idx >> 10, o = idx & 1023;
    const float* W  = kv ? Wv : Wk;
    const float* Ap = g_A  + (kv*Bv + b)*(RKv*Dv);
    const float* Bp = g_Bm + (kv*Bv + b)*(Dv*RKv);
    float acc = 0.f;
    #pragma unroll
    for (int r = 0; r < RKv; r++) acc += Ap[r*Dv + d] * Bp[o*RKv + r];
    g_Weff[((long)(kv*Bv + b))*(Dv*Dv) + idx] = W[idx] + 0.125f * acc;
}

// ---------------- 4) tf32 mma.sync GEMM: C = A(MxK) @ W(KxN) + bias ----------------
// 128x128 tile, 8 warps (2m x 4n), 64x32 per warp, k-chunk 32, double-buffered smem.
#define KC 32
#define APAD 36
#define BPAD 136
#define ASZ (128*APAD)
#define BSZ (32*BPAD)
#define GEMM_SMEM ((ASZ+BSZ)*2*4)

__global__ void __launch_bounds__(256) mma_gemm(
    const float* __restrict__ A, const float* __restrict__ W,
    const float* __restrict__ bias, float* __restrict__ C,
    int M, int N, int K, long sA, long sW, long sC)
{
    extern __shared__ float sm[];
    A += (long)blockIdx.z * sA;
    W += (long)blockIdx.z * sW;
    C += (long)blockIdx.z * sC;
    const int tid = threadIdx.x;
    const int wid = tid >> 5, lane = tid & 31;
    const int tile_m = blockIdx.y * 128;
    const int tile_n = blockIdx.x * 128;
    const int wm = (wid >> 2) * 64;       // warp m offset
    const int wn = (wid & 3) * 32;        // warp n offset
    const int r  = lane >> 2;             // 0..7
    const int qd = lane & 3;              // 0..3

    // global load mapping
    const int a_m  = tid >> 3;            // 0..31 (+32*i)
    const int a_kq = tid & 7;             // k float4 index
    const int b_k  = tid >> 3;            // 0..31
    const int b_nq = tid & 7;             // n float4 index (+8*j)

    const float* Ag = A + (long)(tile_m + a_m)*K + a_kq*4;
    const float* Wg = W + (long)b_k*N + tile_n + b_nq*4;

    float4 aR[4], bR[4];
    // prefetch chunk 0
    #pragma unroll
    for (int i = 0; i < 4; i++) aR[i] = *(const float4*)(Ag + (long)32*i*K);
    #pragma unroll
    for (int j = 0; j < 4; j++) bR[j] = *(const float4*)(Wg + 32*j);

    float acc[4][4][4];
    #pragma unroll
    for (int mi = 0; mi < 4; mi++)
        #pragma unroll
        for (int ni = 0; ni < 4; ni++)
            #pragma unroll
            for (int t = 0; t < 4; t++) acc[mi][ni][t] = 0.f;

    const int NCk = K / KC;
    for (int c = 0; c < NCk; c++) {
        const int buf = c & 1;
        float* As = sm + buf*(ASZ + BSZ);
        float* Bs = As + ASZ;
        // STS chunk c (cvt to tf32)
        #pragma unroll
        for (int i = 0; i < 4; i++) {
            float4 v;
            v.x = to_tf32(aR[i].x); v.y = to_tf32(aR[i].y);
            v.z = to_tf32(aR[i].z); v.w = to_tf32(aR[i].w);
            *(float4*)(As + (a_m + 32*i)*APAD + a_kq*4) = v;
        }
        #pragma unroll
        for (int j = 0; j < 4; j++) {
            float4 v;
            v.x = to_tf32(bR[j].x); v.y = to_tf32(bR[j].y);
            v.z = to_tf32(bR[j].z); v.w = to_tf32(bR[j].w);
            *(float4*)(Bs + b_k*BPAD + b_nq*4 + 32*j) = v;
        }
        __syncthreads();
        // prefetch chunk c+1
        if (c + 1 < NCk) {
            const long ko = (long)(c + 1) * 32;
            #pragma unroll
            for (int i = 0; i < 4; i++) aR[i] = *(const float4*)(Ag + ko + (long)32*i*K);
            #pragma unroll
            for (int j = 0; j < 4; j++) bR[j] = *(const float4*)(Wg + ko*N + 32*j);
        }
        // compute chunk c
        #pragma unroll
        for (int kk = 0; kk < 4; kk++) {
            uint32_t af[4][4];
            #pragma unroll
            for (int mi = 0; mi < 4; mi++) {
                const float* ap = As + (wm + mi*16 + r)*APAD + kk*8 + qd;
                af[mi][0] = __float_as_uint(ap[0]);
                af[mi][1] = __float_as_uint(ap[8*APAD]);
                af[mi][2] = __float_as_uint(ap[4]);
                af[mi][3] = __float_as_uint(ap[8*APAD + 4]);
            }
            #pragma unroll
            for (int ni = 0; ni < 4; ni++) {
                const float* bp = Bs + (kk*8 + qd)*BPAD + wn + ni*8 + r;
                uint32_t b0 = __float_as_uint(bp[0]);
                uint32_t b1 = __float_as_uint(bp[4*BPAD]);
                #pragma unroll
                for (int mi = 0; mi < 4; mi++)
                    MMA_TF32(acc[mi][ni], af[mi], b0, b1);
            }
        }
        __syncthreads();
    }

    // epilogue: direct STG with bias
    #pragma unroll
    for (int mi = 0; mi < 4; mi++) {
        const int row0 = tile_m + wm + mi*16 + r;
        #pragma unroll
        for (int ni = 0; ni < 4; ni++) {
            const int col = tile_n + wn + ni*8 + 2*qd;
            const float bx = __ldg(bias + col), by = __ldg(bias + col + 1);
            float2 v0, v1;
            v0.x = acc[mi][ni][0] + bx; v0.y = acc[mi][ni][1] + by;
            v1.x = acc[mi][ni][2] + bx; v1.y = acc[mi][ni][3] + by;
            *(float2*)(C + (long)row0*N + col)     = v0;
            *(float2*)(C + (long)(row0+8)*N + col) = v1;
        }
    }
}

// ---------------- 5) rope + head-split transpose ----------------
__global__ void rope_kernel() {
    int idx = blockIdx.x*256 + threadIdx.x;
    int d2 = idx & 31;
    int s  = (idx >> 5) & 2047;
    int h  = (idx >> 16) & 15;
    int b  = idx >> 20;
    long src = ((long)(b*Sv + s))*Dv + h*HDv;
    long dst = ((long)((b*Hv + h)*Sv + s))*HDv;
    float inv = expf(-((float)d2 * (1.f/32.f)) * 9.210340371976184f);
    float ang = (float)s * inv;
    float sn, cs;
    sincosf(ang, &sn, &cs);
    float q0 = g_q[src + d2], q1 = g_q[src + d2 + 32];
    g_qh[dst + d2]      = q0*cs - q1*sn;
    g_qh[dst + d2 + 32] = q1*cs + q0*sn;
    float k0 = g_k[src + d2], k1 = g_k[src + d2 + 32];
    g_kh[dst + d2]      = k0*cs - k1*sn;
    g_kh[dst + d2 + 32] = k1*cs + k0*sn;
    g_vh[dst + d2]      = g_v[src + d2];
    g_vh[dst + d2 + 32] = g_v[src + d2 + 32];
}

// ---------------- 6) causal flash attention (fp32, 64x64 tiles) ----------------
#define FLASH_SMEM_FLOATS (64*65*3 + 64*64 + 3*64)
__global__ void __launch_bounds__(256) flash_kernel(
    const float* __restrict__ Q, const float* __restrict__ K,
    const float* __restrict__ V, float* __restrict__ Out)
{
    extern __shared__ float fsm[];
    float* Qt   = fsm;
    float* Kt   = Qt + 64*65;
    float* Vs   = Kt + 64*65;
    float* Ss   = Vs + 64*64;
    float* mrow = Ss + 64*65;
    float* lrow = mrow + 64;
    float* arow = lrow + 64;

    const int qt = blockIdx.x;
    const int bh = blockIdx.y;
    const int tid = threadIdx.x;
    const int ty = tid >> 4, tx = tid & 15;

    const float* Qb = Q + ((long)bh*Sv + qt*64)*HDv;
    const float* Kb = K + (long)bh*Sv*HDv;
    const float* Vb = V + (long)bh*Sv*HDv;

    #pragma unroll
    for (int it = 0; it < 4; it++) {
        int i = tid + it*256;
        int r = i >> 4, d4 = (i & 15)*4;
        float4 qv = *(const float4*)(Qb + r*HDv + d4);
        Qt[(d4+0)*65 + r] = qv.x; Qt[(d4+1)*65 + r] = qv.y;
        Qt[(d4+2)*65 + r] = qv.z; Qt[(d4+3)*65 + r] = qv.w;
    }
    if (tid < 64) { mrow[tid] = -1e30f; lrow[tid] = 0.f; }

    float oacc[4][4];
    #pragma unroll
    for (int i = 0; i < 4; i++)
        #pragma unroll
        for (int j = 0; j < 4; j++) oacc[i][j] = 0.f;

    for (int jt = 0; jt <= qt; jt++) {
        #pragma unroll
        for (int it = 0; it < 4; it++) {
            int i = tid + it*256;
            int r = i >> 4, d4 = (i & 15)*4;
            float4 k4 = *(const float4*)(Kb + ((long)(jt*64 + r))*HDv + d4);
            Kt[(d4+0)*65 + r] = k4.x; Kt[(d4+1)*65 + r] = k4.y;
            Kt[(d4+2)*65 + r] = k4.z; Kt[(d4+3)*65 + r] = k4.w;
            float4 v4 = *(const float4*)(Vb + ((long)(jt*64 + r))*HDv + d4);
            *(float4*)(Vs + r*64 + d4) = v4;
        }
        __syncthreads();

        float sacc[4][4];
        #pragma unroll
        for (int i = 0; i < 4; i++)
            #pragma unroll
            for (int j = 0; j < 4; j++) sacc[i][j] = 0.f;
        #pragma unroll 8
        for (int d = 0; d < 64; d++) {
            const float* qr = Qt + d*65 + ty*4;
            const float* kr = Kt + d*65 + tx*4;
            float a0 = qr[0], a1 = qr[1], a2 = qr[2], a3 = qr[3];
            float b0 = kr[0], b1 = kr[1], b2 = kr[2], b3 = kr[3];
            sacc[0][0] += a0*b0; sacc[0][1] += a0*b1; sacc[0][2] += a0*b2; sacc[0][3] += a0*b3;
            sacc[1][0] += a1*b0; sacc[1][1] += a1*b1; sacc[1][2] += a1*b2; sacc[1][3] += a1*b3;
            sacc[2][0] += a2*b0; sacc[2][1] += a2*b1; sacc[2][2] += a2*b2; sacc[2][3] += a2*b3;
            sacc[3][0] += a3*b0; sacc[3][1] += a3*b1; sacc[3][2] += a3*b2; sacc[3][3] += a3*b3;
        }
        #pragma unroll
        for (int i = 0; i < 4; i++) {
            int rr = ty*4 + i;
            #pragma unroll
            for (int j = 0; j < 4; j++) {
                int c = tx*4 + j;
                float s = sacc[i][j] * 0.125f;
                if (jt == qt && c > rr) s = -1e30f;
                Ss[rr*65 + c] = s;
            }
        }
        __syncthreads();

        {
            int rr = tid >> 2, q4 = tid & 3;
            float* row = Ss + rr*65 + q4*16;
            float vb[16];
            float mx = -1e30f;
            #pragma unroll
            for (int t = 0; t < 16; t++) { vb[t] = row[t]; mx = fmaxf(mx, vb[t]); }
            mx = fmaxf(mx, __shfl_xor_sync(0xffffffffu, mx, 1));
            mx = fmaxf(mx, __shfl_xor_sync(0xffffffffu, mx, 2));
            float mold = mrow[rr];
            float mnew = fmaxf(mold, mx);
            float ls = 0.f;
            #pragma unroll
            for (int t = 0; t < 16; t++) {
                float p = __expf(vb[t] - mnew);
                row[t] = p; ls += p;
            }
            ls += __shfl_xor_sync(0xffffffffu, ls, 1);
            ls += __shfl_xor_sync(0xffffffffu, ls, 2);
            if (q4 == 0) {
                float al = __expf(mold - mnew);
                arow[rr] = al;
                mrow[rr] = mnew;
                lrow[rr] = lrow[rr]*al + ls;
            }
        }
        __syncthreads();

        #pragma unroll
        for (int i = 0; i < 4; i++) {
            float al = arow[ty*4 + i];
            #pragma unroll
            for (int j = 0; j < 4; j++) oacc[i][j] *= al;
        }
        #pragma unroll 8
        for (int kk = 0; kk < 64; kk++) {
            float p0 = Ss[(ty*4+0)*65 + kk];
            float p1 = Ss[(ty*4+1)*65 + kk];
            float p2 = Ss[(ty*4+2)*65 + kk];
            float p3 = Ss[(ty*4+3)*65 + kk];
            float4 vv = *(const float4*)(Vs + kk*64 + tx*4);
            oacc[0][0] += p0*vv.x; oacc[0][1] += p0*vv.y; oacc[0][2] += p0*vv.z; oacc[0][3] += p0*vv.w;
            oacc[1][0] += p1*vv.x; oacc[1][1] += p1*vv.y; oacc[1][2] += p1*vv.z; oacc[1][3] += p1*vv.w;
            oacc[2][0] += p2*vv.x; oacc[2][1] += p2*vv.y; oacc[2][2] += p2*vv.z; oacc[2][3] += p2*vv.w;
            oacc[3][0] += p3*vv.x; oacc[3][1] += p3*vv.y; oacc[3][2] += p3*vv.z; oacc[3][3] += p3*vv.w;
        }
        __syncthreads();
    }

    const int b = bh >> 4, h = bh & 15;
    #pragma unroll
    for (int i = 0; i < 4; i++) {
        int srow = qt*64 + ty*4 + i;
        float inv_l = 1.f / lrow[ty*4 + i];
        #pragma unroll
        for (int j = 0; j < 4; j++)
            Out[((long)(b*Sv + srow))*Dv + h*HDv + tx*4 + j] = oacc[i][j] * inv_l;
    }
}

// ---------------- launch ----------------
extern "C" void kernel_launch(void* const* d_in, const int* in_sizes, int n_in,
                              void* d_out, int out_size) {
    const float* x      = (const float*)d_in[0];
    const float* Wq     = (const float*)d_in[1];
    const float* bq     = (const float*)d_in[2];
    const float* Wo     = (const float*)d_in[3];
    const float* bo     = (const float*)d_in[4];
    const float* Wk     = (const float*)d_in[5];
    const float* bk     = (const float*)d_in[6];
    const float* k_w1   = (const float*)d_in[7];
    const float* k_b1   = (const float*)d_in[8];
    const float* k_w2   = (const float*)d_in[9];
    const float* k_b2   = (const float*)d_in[10];
    const float* k_gA_w = (const float*)d_in[11];
    const float* k_gA_b = (const float*)d_in[12];
    const float* k_gB_w = (const float*)d_in[13];
    const float* k_gB_b = (const float*)d_in[14];
    const float* Wv     = (const float*)d_in[15];
    const float* bv     = (const float*)d_in[16];
    const float* v_w1   = (const float*)d_in[17];
    const float* v_b1   = (const float*)d_in[18];
    const float* v_w2   = (const float*)d_in[19];
    const float* v_b2   = (const float*)d_in[20];
    const float* v_gA_w = (const float*)d_in[21];
    const float* v_gA_b = (const float*)d_in[22];
    const float* v_gB_w = (const float*)d_in[23];
    const float* v_gB_b = (const float*)d_in[24];
    float* out = (float*)d_out;

    float *p_weff, *p_q, *p_k, *p_v, *p_qh, *p_kh, *p_vh, *p_attn;
    cudaGetSymbolAddress((void**)&p_weff, g_Weff);
    cudaGetSymbolAddress((void**)&p_q,    g_q);
    cudaGetSymbolAddress((void**)&p_k,    g_k);
    cudaGetSymbolAddress((void**)&p_v,    g_v);
    cudaGetSymbolAddress((void**)&p_qh,   g_qh);
    cudaGetSymbolAddress((void**)&p_kh,   g_kh);
    cudaGetSymbolAddress((void**)&p_vh,   g_vh);
    cudaGetSymbolAddress((void**)&p_attn, g_attn);

    const int flash_smem = FLASH_SMEM_FLOATS * 4;
    cudaFuncSetAttribute(flash_kernel, cudaFuncAttributeMaxDynamicSharedMemorySize, flash_smem);
    cudaFuncSetAttribute(mma_gemm, cudaFuncAttributeMaxDynamicSharedMemorySize, GEMM_SMEM);

    pool_partial<<<dim3(4, 8, Bv), 256>>>(x);
    pool_combine<<<8, 256>>>();
    hyp_h<<<dim3(2, Bv), HIDv>>>(k_w1, k_b1, v_w1, v_b1);
    hyp_c<<<dim3(2, Bv), DYNv>>>(k_w2, k_b2, v_w2, v_b2);
    hyp_AB<<<dim3(2, Bv, 64), 256>>>(k_gA_w, k_gA_b, k_gB_w, k_gB_b,
                                     v_gA_w, v_gA_b, v_gB_w, v_gB_b);
    weff_kernel<<<dim3(4096, Bv, 2), 256>>>(Wk, Wv);

    // q = x @ Wq + bq
    mma_gemm<<<dim3(8, 32, 1), 256, GEMM_SMEM>>>(x, Wq, bq, p_q, Mv, Dv, Dv, 0, 0, 0);
    // k = x @ Weff_k[b] + bk
    mma_gemm<<<dim3(8, 16, Bv), 256, GEMM_SMEM>>>(x, p_weff, bk, p_k, Sv, Dv, Dv,
                                                  (long)Sv*Dv, (long)Dv*Dv, (long)Sv*Dv);
    // v = x @ Weff_v[b] + bv
    mma_gemm<<<dim3(8, 16, Bv), 256, GEMM_SMEM>>>(x, p_weff + (long)Bv*Dv*Dv, bv, p_v, Sv, Dv, Dv,
                                                  (long)Sv*Dv, (long)Dv*Dv, (long)Sv*Dv);

    rope_kernel<<<8192, 256>>>();

    flash_kernel<<<dim3(32, 32), 256, flash_smem>>>(p_qh, p_kh, p_vh, p_attn);

    // out = attn @ Wo + bo
    mma_gemm<<<dim3(8, 32, 1), 256, GEMM_SMEM>>>(p_attn, Wo, bo, out, Mv, Dv, Dv, 0, 0, 0);
}

// round 4
// speedup vs baseline: 2.8701x; 1.9798x over previous
#include <cuda_runtime.h>
#include <math.h>
#include <stdint.h>

#define Bv 2
#define Sv 2048
#define Dv 1024
#define Hv 16
#define HDv 64
#define HIDv 256
#define DYNv 64
#define RKv 8
#define Mv (Bv*Sv)

__device__ __forceinline__ float to_tf32(float x) {
    float r; asm("cvt.rna.tf32.f32 %0, %1;" : "=f"(r) : "f"(x)); return r;
}
__device__ __forceinline__ float ex2(float x) {
    float r; asm("ex2.approx.f32 %0, %1;" : "=f"(r) : "f"(x)); return r;
}

#define MMA_TF32(d, a, b0, b1) \
  asm volatile("mma.sync.aligned.m16n8k8.row.col.f32.tf32.tf32.f32 " \
    "{%0,%1,%2,%3}, {%4,%5,%6,%7}, {%8,%9}, {%0,%1,%2,%3};" \
    : "+f"((d)[0]), "+f"((d)[1]), "+f"((d)[2]), "+f"((d)[3]) \
    : "r"((a)[0]), "r"((a)[1]), "r"((a)[2]), "r"((a)[3]), "r"(b0), "r"(b1))

// ---------------- scratch ----------------
__device__ float g_zpart[Bv*8*Dv];
__device__ float g_z[Bv*Dv];
__device__ float g_h[2*Bv*HIDv];
__device__ float g_c[2*Bv*DYNv];
__device__ float g_A[2*Bv*RKv*Dv];
__device__ float g_Bm[2*Bv*Dv*RKv];
__device__ float g_Weff[2*Bv*Dv*Dv];
__device__ float g_q[Mv*Dv];
__device__ float g_k[Mv*Dv];
__device__ float g_v[Mv*Dv];
__device__ float g_qh[Mv*Dv];
__device__ float g_kh[Mv*Dv];
__device__ float g_vh[Mv*Dv];
__device__ float g_attn[Mv*Dv];

// ---------------- 1) pooled context ----------------
__global__ void pool_partial(const float* __restrict__ x) {
    int d = blockIdx.x*256 + threadIdx.x;
    int split = blockIdx.y;
    int b = blockIdx.z;
    const float* xp = x + ((long)b*Sv + split*256)*Dv + d;
    float acc = 0.f;
    #pragma unroll 8
    for (int s = 0; s < 256; s++) acc += xp[(long)s*Dv];
    g_zpart[(b*8 + split)*Dv + d] = acc;
}
__global__ void pool_combine() {
    int idx = blockIdx.x*256 + threadIdx.x;
    int b = idx >> 10, d = idx & 1023;
    float acc = 0.f;
    #pragma unroll
    for (int p = 0; p < 8; p++) acc += g_zpart[(b*8 + p)*Dv + d];
    g_z[idx] = acc * (1.f / (float)Sv);
}

// ---------------- 2) hyper-network MLP (K-split parallel) ----------------
__global__ void __launch_bounds__(1024) hyp_h(
    const float* __restrict__ k_w1, const float* __restrict__ k_b1,
    const float* __restrict__ v_w1, const float* __restrict__ v_b1) {
    __shared__ float zs[Dv];
    __shared__ float part[1024];
    int kv = blockIdx.x, b = blockIdx.y, tid = threadIdx.x;
    const float* w1 = kv ? v_w1 : k_w1;
    const float* b1 = kv ? v_b1 : k_b1;
    zs[tid] = g_z[b*Dv + tid];
    __syncthreads();
    int j = tid & 255, ks = tid >> 8;
    float acc = 0.f;
    const float* wp = w1 + (long)(ks*256)*HIDv + j;
    #pragma unroll 8
    for (int dd = 0; dd < 256; dd++) acc += zs[ks*256 + dd] * wp[(long)dd*HIDv];
    part[tid] = acc;
    __syncthreads();
    if (ks == 0) {
        float a = part[j] + part[256 + j] + part[512 + j] + part[768 + j] + b1[j];
        float sg = 1.f / (1.f + __expf(-a));
        g_h[(kv*Bv + b)*HIDv + j] = a * sg;
    }
}
__global__ void __launch_bounds__(256) hyp_c(
    const float* __restrict__ k_w2, const float* __restrict__ k_b2,
    const float* __restrict__ v_w2, const float* __restrict__ v_b2) {
    __shared__ float hs[HIDv];
    __shared__ float part[256];
    int kv = blockIdx.x, b = blockIdx.y, tid = threadIdx.x;
    const float* w2 = kv ? v_w2 : k_w2;
    const float* b2 = kv ? v_b2 : k_b2;
    hs[tid] = g_h[(kv*Bv + b)*HIDv + tid];
    __syncthreads();
    int j = tid & 63, ks = tid >> 6;
    float acc = 0.f;
    const float* wp = w2 + (long)(ks*64)*DYNv + j;
    #pragma unroll 8
    for (int i = 0; i < 64; i++) acc += hs[ks*64 + i] * wp[(long)i*DYNv];
    part[tid] = acc;
    __syncthreads();
    if (ks == 0)
        g_c[(kv*Bv + b)*DYNv + j] = part[j] + part[64+j] + part[128+j] + part[192+j] + b2[j];
}
__global__ void hyp_AB(const float* __restrict__ kAw, const float* __restrict__ kAb,
                       const float* __restrict__ kBw, const float* __restrict__ kBb,
                       const float* __restrict__ vAw, const float* __restrict__ vAb,
                       const float* __restrict__ vBw, const float* __restrict__ vBb) {
    __shared__ float cs[DYNv];
    int kv = blockIdx.x, b = blockIdx.y, chunk = blockIdx.z;
    if (threadIdx.x < DYNv) cs[threadIdx.x] = g_c[(kv*Bv + b)*DYNv + threadIdx.x];
    __syncthreads();
    bool isA = chunk < 32;
    int j = (isA ? chunk : chunk - 32)*256 + threadIdx.x;
    const float* w  = isA ? (kv ? vAw : kAw) : (kv ? vBw : kBw);
    const float* bb = isA ? (kv ? vAb : kAb) : (kv ? vBb : kBb);
    float acc = bb[j];
    #pragma unroll 8
    for (int t = 0; t < DYNv; t++) acc += cs[t] * w[t*(RKv*Dv) + j];
    float* dst = isA ? g_A : g_Bm;
    dst[(kv*Bv + b)*(RKv*Dv) + j] = acc;
}

// ---------------- 3) fold low-rank into effective weight ----------------
__global__ void weff_kernel(const float* __restrict__ Wk, const float* __restrict__ Wv) {
    __shared__ float sB[256*RKv];
    int kv = blockIdx.z, b = blockIdx.y, tid = threadIdx.x;
    int d = blockIdx.x >> 2;
    int obase = (blockIdx.x & 3) * 256;
    const float* W  = kv ? Wv : Wk;
    const float* Ap = g_A  + (kv*Bv + b)*(RKv*Dv);
    const float* Bp = g_Bm + (kv*Bv + b)*(Dv*RKv) + obase*RKv;
    #pragma unroll
    for (int i = 0; i < 8; i++) sB[i*256 + tid] = Bp[i*256 + tid];
    __syncthreads();
    float acc = 0.f;
    #pragma unroll
    for (int r = 0; r < RKv; r++) acc += Ap[r*Dv + d] * sB[tid*RKv + r];
    long idx = (long)d*Dv + obase + tid;
    g_Weff[((long)(kv*Bv + b))*(Dv*Dv) + idx] = W[idx] + 0.125f * acc;
}

// ---------------- 4) tf32 mma.sync GEMM: C = A(MxK) @ W(KxN) + bias ----------------
#define KC 32
#define APAD 36
#define BPAD 136
#define ASZ (128*APAD)
#define BSZ (32*BPAD)
#define GEMM_SMEM ((ASZ+BSZ)*2*4)

__global__ void __launch_bounds__(256) mma_gemm(
    const float* __restrict__ A, const float* __restrict__ W,
    const float* __restrict__ bias, float* __restrict__ C,
    int M, int N, int K, long sA, long sW, long sC)
{
    extern __shared__ float sm[];
    A += (long)blockIdx.z * sA;
    W += (long)blockIdx.z * sW;
    C += (long)blockIdx.z * sC;
    const int tid = threadIdx.x;
    const int wid = tid >> 5, lane = tid & 31;
    const int tile_m = blockIdx.y * 128;
    const int tile_n = blockIdx.x * 128;
    const int wm = (wid >> 2) * 64;
    const int wn = (wid & 3) * 32;
    const int r  = lane >> 2;
    const int qd = lane & 3;

    const int a_m  = tid >> 3;
    const int a_kq = tid & 7;
    const int b_k  = tid >> 3;
    const int b_nq = tid & 7;

    const float* Ag = A + (long)(tile_m + a_m)*K + a_kq*4;
    const float* Wg = W + (long)b_k*N + tile_n + b_nq*4;

    float4 aR[4], bR[4];
    #pragma unroll
    for (int i = 0; i < 4; i++) aR[i] = *(const float4*)(Ag + (long)32*i*K);
    #pragma unroll
    for (int j = 0; j < 4; j++) bR[j] = *(const float4*)(Wg + 32*j);

    float acc[4][4][4];
    #pragma unroll
    for (int mi = 0; mi < 4; mi++)
        #pragma unroll
        for (int ni = 0; ni < 4; ni++)
            #pragma unroll
            for (int t = 0; t < 4; t++) acc[mi][ni][t] = 0.f;

    const int NCk = K / KC;
    for (int c = 0; c < NCk; c++) {
        const int buf = c & 1;
        float* As = sm + buf*(ASZ + BSZ);
        float* Bs = As + ASZ;
        #pragma unroll
        for (int i = 0; i < 4; i++) {
            float4 v;
            v.x = to_tf32(aR[i].x); v.y = to_tf32(aR[i].y);
            v.z = to_tf32(aR[i].z); v.w = to_tf32(aR[i].w);
            *(float4*)(As + (a_m + 32*i)*APAD + a_kq*4) = v;
        }
        #pragma unroll
        for (int j = 0; j < 4; j++) {
            float4 v;
            v.x = to_tf32(bR[j].x); v.y = to_tf32(bR[j].y);
            v.z = to_tf32(bR[j].z); v.w = to_tf32(bR[j].w);
            *(float4*)(Bs + b_k*BPAD + b_nq*4 + 32*j) = v;
        }
        __syncthreads();
        if (c + 1 < NCk) {
            const long ko = (long)(c + 1) * 32;
            #pragma unroll
            for (int i = 0; i < 4; i++) aR[i] = *(const float4*)(Ag + ko + (long)32*i*K);
            #pragma unroll
            for (int j = 0; j < 4; j++) bR[j] = *(const float4*)(Wg + ko*N + 32*j);
        }
        #pragma unroll
        for (int kk = 0; kk < 4; kk++) {
            uint32_t af[4][4];
            #pragma unroll
            for (int mi = 0; mi < 4; mi++) {
                const float* ap = As + (wm + mi*16 + r)*APAD + kk*8 + qd;
                af[mi][0] = __float_as_uint(ap[0]);
                af[mi][1] = __float_as_uint(ap[8*APAD]);
                af[mi][2] = __float_as_uint(ap[4]);
                af[mi][3] = __float_as_uint(ap[8*APAD + 4]);
            }
            #pragma unroll
            for (int ni = 0; ni < 4; ni++) {
                const float* bp = Bs + (kk*8 + qd)*BPAD + wn + ni*8 + r;
                uint32_t b0 = __float_as_uint(bp[0]);
                uint32_t b1 = __float_as_uint(bp[4*BPAD]);
                #pragma unroll
                for (int mi = 0; mi < 4; mi++)
                    MMA_TF32(acc[mi][ni], af[mi], b0, b1);
            }
        }
        __syncthreads();
    }

    #pragma unroll
    for (int mi = 0; mi < 4; mi++) {
        const int row0 = tile_m + wm + mi*16 + r;
        #pragma unroll
        for (int ni = 0; ni < 4; ni++) {
            const int col = tile_n + wn + ni*8 + 2*qd;
            const float bx = __ldg(bias + col), by = __ldg(bias + col + 1);
            float2 v0, v1;
            v0.x = acc[mi][ni][0] + bx; v0.y = acc[mi][ni][1] + by;
            v1.x = acc[mi][ni][2] + bx; v1.y = acc[mi][ni][3] + by;
            *(float2*)(C + (long)row0*N + col)     = v0;
            *(float2*)(C + (long)(row0+8)*N + col) = v1;
        }
    }
}

// ---------------- 5) rope + head-split transpose ----------------
__global__ void rope_kernel() {
    int idx = blockIdx.x*256 + threadIdx.x;
    int d2 = idx & 31;
    int s  = (idx >> 5) & 2047;
    int h  = (idx >> 16) & 15;
    int b  = idx >> 20;
    long src = ((long)(b*Sv + s))*Dv + h*HDv;
    long dst = ((long)((b*Hv + h)*Sv + s))*HDv;
    float inv = expf(-((float)d2 * (1.f/32.f)) * 9.210340371976184f);
    float ang = (float)s * inv;
    float sn, cs;
    sincosf(ang, &sn, &cs);
    float q0 = g_q[src + d2], q1 = g_q[src + d2 + 32];
    g_qh[dst + d2]      = q0*cs - q1*sn;
    g_qh[dst + d2 + 32] = q1*cs + q0*sn;
    float k0 = g_k[src + d2], k1 = g_k[src + d2 + 32];
    g_kh[dst + d2]      = k0*cs - k1*sn;
    g_kh[dst + d2 + 32] = k1*cs + k0*sn;
    g_vh[dst + d2]      = g_v[src + d2];
    g_vh[dst + d2 + 32] = g_v[src + d2 + 32];
}

// ---------------- 6) causal flash attention (tf32 mma, 64 q-rows/CTA) ----------------
#define QPAD 68
#define KPAD 68
#define PPAD 68
#define VPAD 72
#define FQ (64*QPAD)
#define FK (64*KPAD)
#define FP (64*PPAD)
#define FV (64*VPAD)
#define FLASH_SMEM ((FQ + FK + FP + FV)*4)
#define FSCL 0.18033688011112042f   // 0.125 * log2(e)

__global__ void __launch_bounds__(128) flash_mma(
    const float* __restrict__ Q, const float* __restrict__ K,
    const float* __restrict__ V, float* __restrict__ Out)
{
    extern __shared__ float fsm[];
    float* Qs = fsm;          // [64][QPAD] A-operand
    float* Ks = Qs + FQ;      // [64][KPAD] B-operand (row=kv, col=hd)
    float* Ps = Ks + FK;      // [64][PPAD] A-operand
    float* Vs = Ps + FP;      // [64][VPAD] B-operand (row=kv, col=hd)

    const int qt = 31 - blockIdx.x;     // heavy tiles first
    const int bh = blockIdx.y;
    const int tid = threadIdx.x;
    const int warp = tid >> 5, lane = tid & 31;
    const int g = lane >> 2, tig = lane & 3;
    const int r0 = warp*16 + g;

    const float* Qb = Q + ((long)bh*Sv + qt*64)*HDv;
    const float* Kb = K + (long)bh*Sv*HDv;
    const float* Vb = V + (long)bh*Sv*HDv;

    const int lrow = tid >> 4;          // 0..7
    const int lcol = (tid & 15) * 4;

    // load Q tile (tf32)
    #pragma unroll
    for (int it = 0; it < 8; it++) {
        int rr = lrow + it*8;
        float4 qv = *(const float4*)(Qb + rr*HDv + lcol);
        float4 o;
        o.x = to_tf32(qv.x); o.y = to_tf32(qv.y);
        o.z = to_tf32(qv.z); o.w = to_tf32(qv.w);
        *(float4*)(Qs + rr*QPAD + lcol) = o;
    }

    float oa[8][4];
    #pragma unroll
    for (int nt = 0; nt < 8; nt++)
        #pragma unroll
        for (int e = 0; e < 4; e++) oa[nt][e] = 0.f;
    float m0 = -1e30f, m1 = -1e30f, l0 = 0.f, l1 = 0.f;

    for (int jt = 0; jt <= qt; jt++) {
        // load K/V tile (tf32)
        #pragma unroll
        for (int it = 0; it < 8; it++) {
            int rr = lrow + it*8;
            float4 k4 = *(const float4*)(Kb + ((long)(jt*64 + rr))*HDv + lcol);
            float4 ko;
            ko.x = to_tf32(k4.x); ko.y = to_tf32(k4.y);
            ko.z = to_tf32(k4.z); ko.w = to_tf32(k4.w);
            *(float4*)(Ks + rr*KPAD + lcol) = ko;
            float4 v4 = *(const float4*)(Vb + ((long)(jt*64 + rr))*HDv + lcol);
            float4 vo;
            vo.x = to_tf32(v4.x); vo.y = to_tf32(v4.y);
            vo.z = to_tf32(v4.z); vo.w = to_tf32(v4.w);
            *(float4*)(Vs + rr*VPAD + lcol) = vo;
        }
        __syncthreads();

        // S = Q @ K^T (per-warp 16x64)
        float s[8][4];
        #pragma unroll
        for (int nt = 0; nt < 8; nt++)
            #pragma unroll
            for (int e = 0; e < 4; e++) s[nt][e] = 0.f;
        #pragma unroll
        for (int kt = 0; kt < 8; kt++) {
            uint32_t a[4];
            const float* qp = Qs + r0*QPAD + kt*8 + tig;
            a[0] = __float_as_uint(qp[0]);
            a[1] = __float_as_uint(qp[8*QPAD]);
            a[2] = __float_as_uint(qp[4]);
            a[3] = __float_as_uint(qp[8*QPAD + 4]);
            #pragma unroll
            for (int nt = 0; nt < 8; nt++) {
                const float* kp = Ks + (nt*8 + g)*KPAD + kt*8 + tig;
                uint32_t b0 = __float_as_uint(kp[0]);
                uint32_t b1 = __float_as_uint(kp[4]);
                MMA_TF32(s[nt], a, b0, b1);
            }
        }

        // scale to log2 domain + causal mask
        #pragma unroll
        for (int nt = 0; nt < 8; nt++) {
            #pragma unroll
            for (int e = 0; e < 4; e++) s[nt][e] *= FSCL;
            if (jt == qt) {
                int c0 = nt*8 + 2*tig;
                if (c0     > r0)     s[nt][0] = -1e30f;
                if (c0 + 1 > r0)     s[nt][1] = -1e30f;
                if (c0     > r0 + 8) s[nt][2] = -1e30f;
                if (c0 + 1 > r0 + 8) s[nt][3] = -1e30f;
            }
        }

        // online softmax (rows r0, r0+8)
        float mx0 = -1e30f, mx1 = -1e30f;
        #pragma unroll
        for (int nt = 0; nt < 8; nt++) {
            mx0 = fmaxf(mx0, fmaxf(s[nt][0], s[nt][1]));
            mx1 = fmaxf(mx1, fmaxf(s[nt][2], s[nt][3]));
        }
        mx0 = fmaxf(mx0, __shfl_xor_sync(0xffffffffu, mx0, 1));
        mx0 = fmaxf(mx0, __shfl_xor_sync(0xffffffffu, mx0, 2));
        mx1 = fmaxf(mx1, __shfl_xor_sync(0xffffffffu, mx1, 1));
        mx1 = fmaxf(mx1, __shfl_xor_sync(0xffffffffu, mx1, 2));
        float mn0 = fmaxf(m0, mx0), mn1 = fmaxf(m1, mx1);
        float al0 = ex2(m0 - mn0), al1 = ex2(m1 - mn1);
        m0 = mn0; m1 = mn1;
        float ls0 = 0.f, ls1 = 0.f;
        #pragma unroll
        for (int nt = 0; nt < 8; nt++) {
            float p0 = ex2(s[nt][0] - m0);
            float p1 = ex2(s[nt][1] - m0);
            float p2 = ex2(s[nt][2] - m1);
            float p3 = ex2(s[nt][3] - m1);
            ls0 += p0 + p1; ls1 += p2 + p3;
            int c0 = nt*8 + 2*tig;
            float2 w0; w0.x = to_tf32(p0); w0.y = to_tf32(p1);
            float2 w1; w1.x = to_tf32(p2); w1.y = to_tf32(p3);
            *(float2*)(Ps + r0*PPAD + c0)       = w0;
            *(float2*)(Ps + (r0+8)*PPAD + c0)   = w1;
        }
        ls0 += __shfl_xor_sync(0xffffffffu, ls0, 1);
        ls0 += __shfl_xor_sync(0xffffffffu, ls0, 2);
        ls1 += __shfl_xor_sync(0xffffffffu, ls1, 1);
        ls1 += __shfl_xor_sync(0xffffffffu, ls1, 2);
        l0 = l0*al0 + ls0;
        l1 = l1*al1 + ls1;
        #pragma unroll
        for (int nt = 0; nt < 8; nt++) {
            oa[nt][0] *= al0; oa[nt][1] *= al0;
            oa[nt][2] *= al1; oa[nt][3] *= al1;
        }
        __syncwarp();

        // O += P @ V
        #pragma unroll
        for (int kt = 0; kt < 8; kt++) {
            uint32_t a[4];
            const float* pp = Ps + r0*PPAD + kt*8 + tig;
            a[0] = __float_as_uint(pp[0]);
            a[1] = __float_as_uint(pp[8*PPAD]);
            a[2] = __float_as_uint(pp[4]);
            a[3] = __float_as_uint(pp[8*PPAD + 4]);
            #pragma unroll
            for (int nt = 0; nt < 8; nt++) {
                const float* vp = Vs + (kt*8 + tig)*VPAD + nt*8 + g;
                uint32_t b0 = __float_as_uint(vp[0]);
                uint32_t b1 = __float_as_uint(vp[4*VPAD]);
                MMA_TF32(oa[nt], a, b0, b1);
            }
        }
        __syncthreads();
    }

    // write out: (b, s, D) layout
    const int b = bh >> 4, h = bh & 15;
    const float inv0 = 1.f / l0, inv1 = 1.f / l1;
    const int rg0 = qt*64 + r0;
    #pragma unroll
    for (int nt = 0; nt < 8; nt++) {
        int col = h*HDv + nt*8 + 2*tig;
        float2 w0; w0.x = oa[nt][0]*inv0; w0.y = oa[nt][1]*inv0;
        float2 w1; w1.x = oa[nt][2]*inv1; w1.y = oa[nt][3]*inv1;
        *(float2*)(Out + ((long)(b*Sv + rg0))*Dv + col)     = w0;
        *(float2*)(Out + ((long)(b*Sv + rg0 + 8))*Dv + col) = w1;
    }
}

// ---------------- launch ----------------
extern "C" void kernel_launch(void* const* d_in, const int* in_sizes, int n_in,
                              void* d_out, int out_size) {
    const float* x      = (const float*)d_in[0];
    const float* Wq     = (const float*)d_in[1];
    const float* bq     = (const float*)d_in[2];
    const float* Wo     = (const float*)d_in[3];
    const float* bo     = (const float*)d_in[4];
    const float* Wk     = (const float*)d_in[5];
    const float* bk     = (const float*)d_in[6];
    const float* k_w1   = (const float*)d_in[7];
    const float* k_b1   = (const float*)d_in[8];
    const float* k_w2   = (const float*)d_in[9];
    const float* k_b2   = (const float*)d_in[10];
    const float* k_gA_w = (const float*)d_in[11];
    const float* k_gA_b = (const float*)d_in[12];
    const float* k_gB_w = (const float*)d_in[13];
    const float* k_gB_b = (const float*)d_in[14];
    const float* Wv     = (const float*)d_in[15];
    const float* bv     = (const float*)d_in[16];
    const float* v_w1   = (const float*)d_in[17];
    const float* v_b1   = (const float*)d_in[18];
    const float* v_w2   = (const float*)d_in[19];
    const float* v_b2   = (const float*)d_in[20];
    const float* v_gA_w = (const float*)d_in[21];
    const float* v_gA_b = (const float*)d_in[22];
    const float* v_gB_w = (const float*)d_in[23];
    const float* v_gB_b = (const float*)d_in[24];
    float* out = (float*)d_out;

    float *p_weff, *p_q, *p_k, *p_v, *p_qh, *p_kh, *p_vh, *p_attn;
    cudaGetSymbolAddress((void**)&p_weff, g_Weff);
    cudaGetSymbolAddress((void**)&p_q,    g_q);
    cudaGetSymbolAddress((void**)&p_k,    g_k);
    cudaGetSymbolAddress((void**)&p_v,    g_v);
    cudaGetSymbolAddress((void**)&p_qh,   g_qh);
    cudaGetSymbolAddress((void**)&p_kh,   g_kh);
    cudaGetSymbolAddress((void**)&p_vh,   g_vh);
    cudaGetSymbolAddress((void**)&p_attn, g_attn);

    cudaFuncSetAttribute(flash_mma, cudaFuncAttributeMaxDynamicSharedMemorySize, FLASH_SMEM);
    cudaFuncSetAttribute(mma_gemm, cudaFuncAttributeMaxDynamicSharedMemorySize, GEMM_SMEM);

    pool_partial<<<dim3(4, 8, Bv), 256>>>(x);
    pool_combine<<<8, 256>>>();
    hyp_h<<<dim3(2, Bv), 1024>>>(k_w1, k_b1, v_w1, v_b1);
    hyp_c<<<dim3(2, Bv), 256>>>(k_w2, k_b2, v_w2, v_b2);
    hyp_AB<<<dim3(2, Bv, 64), 256>>>(k_gA_w, k_gA_b, k_gB_w, k_gB_b,
                                     v_gA_w, v_gA_b, v_gB_w, v_gB_b);
    weff_kernel<<<dim3(4096, Bv, 2), 256>>>(Wk, Wv);

    mma_gemm<<<dim3(8, 32, 1), 256, GEMM_SMEM>>>(x, Wq, bq, p_q, Mv, Dv, Dv, 0, 0, 0);
    mma_gemm<<<dim3(8, 16, Bv), 256, GEMM_SMEM>>>(x, p_weff, bk, p_k, Sv, Dv, Dv,
                                                  (long)Sv*Dv, (long)Dv*Dv, (long)Sv*Dv);
    mma_gemm<<<dim3(8, 16, Bv), 256, GEMM_SMEM>>>(x, p_weff + (long)Bv*Dv*Dv, bv, p_v, Sv, Dv, Dv,
                                                  (long)Sv*Dv, (long)Dv*Dv, (long)Sv*Dv);

    rope_kernel<<<8192, 256>>>();

    flash_mma<<<dim3(32, 32), 128, FLASH_SMEM>>>(p_qh, p_kh, p_vh, p_attn);

    mma_gemm<<<dim3(8, 32, 1), 256, GEMM_SMEM>>>(p_attn, Wo, bo, out, Mv, Dv, Dv, 0, 0, 0);
}